// round 13
// baseline (speedup 1.0000x reference)
#include <cuda_runtime.h>
#include <cstdint>
#include <cstddef>

// Problem shape (fixed by setup_inputs)
#define B_    8
#define S_    4096
#define D_    1024

#define SEGR  128                // rows per segment (block)
#define NSEG  (S_ / SEGR)        // 32 segments
#define WPB   4                  // warps per block; warp owns 128 cols
#define NTHR  (WPB * 32)         // 128 threads
#define CHK   8                  // rows per pipeline chunk (4 KB per warp)
#define NBUF  3                  // pipeline depth
#define RS4   (D_ / 4)           // row stride in float4 (256)
#define NCHN  64                 // (batch, 128-col slice) chains = 8*8

// Cross-segment handoff. Zero-init at load; producer sets, unique consumer
// clears -> invariant across graph replays (no clear kernel needed).
__device__ volatile int g_run[B_][2][NSEG];     // runlen+1 leaving seg; 0=unready
__device__ volatile int g_sf[NCHN][NSEG];       // final S published
__device__ float4       g_sv[NCHN][NSEG][32];   // final S per lane (1 MB)

struct __align__(16) Smem {
    float4   xs[WPB][NBUF][CHK][32];   // 48 KB per-warp pipeline buffers
    float4   tbl[SEGR];                // 2 KB (m, n, 1/n, _) per row
    unsigned rmask[WPB];
    int      s_fr, s_carry, modeAcc;
};                                      // ~50.3 KB -> 4 blocks/SM

__device__ __forceinline__ unsigned smem_u32(const void* p) {
    return (unsigned)__cvta_generic_to_shared(p);
}
__device__ __forceinline__ void cp16(unsigned dst, const void* src) {
    asm volatile("cp.async.cg.shared.global [%0], [%1], 16;\n" :: "r"(dst), "l"(src));
}
__device__ __forceinline__ void cp_commit() {
    asm volatile("cp.async.commit_group;\n");
}
template <int N>
__device__ __forceinline__ void cp_wait_n() {
    asm volatile("cp.async.wait_group %0;\n" :: "n"(N) : "memory");
}

__global__ void __launch_bounds__(NTHR, 4)
scan_kernel(const float* __restrict__ emb,
            const int*   __restrict__ idw,      // raw 32-bit word view of ids
            float* __restrict__ out)
{
    extern __shared__ char raw[];
    Smem* sm = reinterpret_cast<Smem*>(raw);

    const int tid = threadIdx.x;
    const int w   = tid >> 5;
    const int l   = tid & 31;

    const int bid = blockIdx.x;                 // seg-major: preds dispatch first
    const int seg = bid >> 4;
    const int u   = bid & 15;
    const int b   = u >> 1;
    const int ch  = u & 1;                      // column half
    const int t0  = seg * SEGR;
    const int cidx = b * 8 + ch * 4 + w;        // warp's chain id

    const float4* xg = (const float4*)emb + ((size_t)(b * S_ + t0)) * RS4
                       + (ch * 4 + w) * 32 + l;
    float4*       og = (float4*)out       + ((size_t)(b * S_ + t0)) * RS4
                       + (ch * 4 + w) * 32 + l;

    // ================= prologue =================
    if (tid == 0) { sm->modeAcc = 0; sm->s_carry = 0; }
    __syncthreads();

    // dtype detect on globally-safe word window [0,2048): odd words are int64
    // hi-halves (all zero) iff ids are int64 with values in [0,64).
    {
        int acc = 0;
        #pragma unroll
        for (int k = 0; k < 8; k++)
            acc |= __ldg(&idw[2 * (tid * 8 + k) + 1]);
        #pragma unroll
        for (int o = 16; o; o >>= 1) acc |= __shfl_xor_sync(~0u, acc, o);
        if (l == 0) atomicOr(&sm->modeAcc, acc);
    }
    __syncthreads();
    const bool mode64 = (sm->modeAcc == 0);

    // reset flags for this segment's 128 rows (row = tid)
    int myf;
    {
        int gi = b * S_ + t0 + tid;
        if (mode64) {
            int2 v = __ldg(((const int2*)idw) + gi);
            myf = (v.x == 1) & (v.y == 0);
        } else {
            myf = (__ldg(idw + gi) == 1);
        }
        unsigned m = __ballot_sync(~0u, myf);
        if (l == 0) sm->rmask[w] = m;
    }
    __syncthreads();

    // fr + early run-length publish + carry consume (all prologue-stage)
    if (tid == 0) {
        int fr = SEGR, last = -1;
        #pragma unroll
        for (int q = 0; q < WPB; q++) {
            unsigned m = sm->rmask[q];
            if (m) {
                if (fr == SEGR) fr = q * 32 + __ffs(m) - 1;
                last = q * 32 + 31 - __clz(m);
            }
        }
        sm->s_fr = fr;
        if (fr < SEGR && seg + 1 < NSEG) {
            __threadfence();
            g_run[b][ch][seg] = (SEGR - last) + 1;   // runlen + 1
        }
        if (seg > 0) {                               // consume predecessor carry
            int v;
            while ((v = g_run[b][ch][seg - 1]) == 0) __nanosleep(64);
            g_run[b][ch][seg - 1] = 0;               // clear for next replay
            sm->s_carry = v - 1;
        }
    }
    __syncthreads();
    const int fr    = sm->s_fr;
    const int carry = sm->s_carry;

    if (fr == SEGR && seg + 1 < NSEG && tid == 0) {  // forward carry (no reset)
        __threadfence();
        g_run[b][ch][seg] = carry + SEGR + 1;
    }

    // full row table: head rows use carry; tail rows use local last-reset
    if (tid < fr) {
        float nf = (float)(carry + tid + 1);
        sm->tbl[tid] = make_float4(1.f, nf, __fdividef(1.f, nf), 0.f);
    } else {
        int q = tid >> 5, li = tid & 31;
        unsigned below = sm->rmask[q] & (0xFFFFFFFFu >> (31 - li));
        int last;
        if (below) last = q * 32 + 31 - __clz(below);
        else {
            last = 0;
            for (int qq = q - 1; qq >= 0; qq--)
                if (sm->rmask[qq]) { last = qq * 32 + 31 - __clz(sm->rmask[qq]); break; }
        }
        float nf = (float)(tid - last + 1);
        sm->tbl[tid] = make_float4(myf ? 0.f : 1.f, nf, __fdividef(1.f, nf), 0.f);
    }
    __syncthreads();   // table ready; warps now fully independent

    // ---- per-warp pipelined streamer over local rows [a, bnd) ----
    auto issue_chunk = [&](int base, int bnd, int buf) {
        #pragma unroll
        for (int j = 0; j < CHK; j++) {
            int row = base + j; row = row < bnd ? row : bnd - 1;  // clamp in-seg
            cp16(smem_u32(&sm->xs[w][buf][j][l]), xg + (size_t)row * RS4);
        }
    };
    auto stream = [&](int a, int bnd, float4 S) -> float4 {
        const int nch = (bnd - a + CHK - 1) / CHK;
        #pragma unroll
        for (int p = 0; p < NBUF; p++) {              // always commit NBUF groups
            if (p < nch) issue_chunk(a + p * CHK, bnd, p);
            cp_commit();
        }
        int buf = 0;
        for (int c = 0; c < nch; ++c) {
            cp_wait_n<NBUF - 1>();                    // chunk c's group complete
            const int r0 = a + c * CHK;
            #pragma unroll
            for (int j = 0; j < CHK; j++) {
                int row = r0 + j;
                if (row < bnd) {
                    float4 t = sm->tbl[row];          // LDS.128 broadcast
                    float4 x = sm->xs[w][buf][j][l];  // LDS.128
                    S.x = fmaf(S.x, t.x, x.x * t.y);
                    S.y = fmaf(S.y, t.x, x.y * t.y);
                    S.z = fmaf(S.z, t.x, x.z * t.y);
                    S.w = fmaf(S.w, t.x, x.w * t.y);
                    og[(size_t)row * RS4] =
                        make_float4(S.x * t.z, S.y * t.z, S.z * t.z, S.w * t.z);
                }
            }
            if (c + NBUF < nch) issue_chunk(a + (c + NBUF) * CHK, bnd, buf);
            cp_commit();                              // one group per iteration
            if (++buf == NBUF) buf = 0;
        }
        cp_wait_n<0>();                               // drain before buffer reuse
        return S;
    };

    // ---- phase 1: exact tail [fr, SEGR) (m=0 at fr kills the seed) ----
    if (fr < SEGR) {
        float4 S = stream(fr, SEGR, make_float4(0, 0, 0, 0));
        if (seg + 1 < NSEG) {
            g_sv[cidx][seg][l] = S;
            __threadfence();
            if (l == 0) g_sf[cidx][seg] = 1;
        }
    }

    // ---- phase 2: head [0, fr) seeded with predecessor's final S ----
    float4 Sin = make_float4(0, 0, 0, 0);
    if (seg > 0) {                                    // consume unconditionally
        if (l == 0) {
            while (g_sf[cidx][seg - 1] == 0) __nanosleep(64);
            g_sf[cidx][seg - 1] = 0;                  // clear for next replay
        }
        __syncwarp();
        __threadfence();
        Sin = g_sv[cidx][seg - 1][l];
    }
    if (fr > 0) {
        float4 Sh = stream(0, fr, Sin);
        if (fr == SEGR && seg + 1 < NSEG) {           // no-reset segment
            g_sv[cidx][seg][l] = Sh;
            __threadfence();
            if (l == 0) g_sf[cidx][seg] = 1;
        }
    }
}

extern "C" void kernel_launch(void* const* d_in, const int* in_sizes, int n_in,
                              void* d_out, int out_size) {
    const float* emb = (const float*)d_in[0];
    const int*   idw = (const int*)d_in[1];
    float*       out = (float*)d_out;

    (void)in_sizes; (void)n_in; (void)out_size;

    cudaFuncSetAttribute(scan_kernel,
                         cudaFuncAttributeMaxDynamicSharedMemorySize,
                         (int)sizeof(Smem));

    scan_kernel<<<NSEG * 16, NTHR, sizeof(Smem)>>>(emb, idw, out);
}